// round 14
// baseline (speedup 1.0000x reference)
#include <cuda_runtime.h>
#include <math.h>
#include <stdint.h>

#define NB    40      // small grid: 8 scanners + 31 workers + 1 tail (<=148 SMs)
#define NT    1024
#define NBL   8       // scanner blocks (labels)
#define TAILB (NB - 1)                 // dedicated tail block
#define NBW   (NB - 1 - NBL)           // worker blocks: 31
#define HC    256     // H*C = 2*128
#define HID   256
#define MAXED 256     // cap on edges into target (expected ~8)

// __device__ scratch. g_count/g_ticket/g_tflag reset by the tail block.
__device__ int      g_target;
__device__ float    g_xt0, g_xt1;
__device__ volatile int g_tflag;       // 0 -> target not yet published
__device__ int      g_count;
__device__ int      g_eid[MAXED];
__device__ float    g_ex0[MAXED], g_ex1[MAXED], g_eea[MAXED];
__device__ volatile unsigned g_ticket; // counts workers that finished

__device__ __forceinline__ void prefetch_l2(const void* p) {
    asm volatile("prefetch.global.L2 [%0];" :: "l"(p));
}

// On a match, fetch everything the tail needs (overlaps other blocks' work).
__device__ __forceinline__ void record_match(
    int eid, const int* src, const float* x, const float* eattr)
{
    int p = atomicAdd(&g_count, 1);
    if (p < MAXED) {
        int s = __ldg(src + eid);
        float2 xs = __ldg((const float2*)(x + 2 * s));
        g_eid[p] = eid;
        g_ex0[p] = xs.x;
        g_ex1[p] = xs.y;
        g_eea[p] = __ldg(eattr + eid);
    }
}

__device__ __forceinline__ void check4(
    int4 v, int base, int target,
    const int* src, const float* x, const float* eattr)
{
    if (v.x == target) record_match(base,     src, x, eattr);
    if (v.y == target) record_match(base + 1, src, x, eattr);
    if (v.z == target) record_match(base + 2, src, x, eattr);
    if (v.w == target) record_match(base + 3, src, x, eattr);
}

// ---------------------------------------------------------------------------
__global__ void __launch_bounds__(NT, 1) gat_kernel(
    const float* __restrict__ x,
    const int*   __restrict__ edge_index,
    const float* __restrict__ eattr,
    const int*   __restrict__ labels,
    const float* __restrict__ Wl,  const float* __restrict__ bl,
    const float* __restrict__ Wr,  const float* __restrict__ br,
    const float* __restrict__ We,  const float* __restrict__ att,
    const float* __restrict__ bo,
    const float* __restrict__ Wfc, const float* __restrict__ bfc,
    float* __restrict__ out, int N, int E)
{
    const int t   = threadIdx.x;
    const int bid = blockIdx.x;
    const int* srcp = edge_index;
    const int* dstp = edge_index + E;

    if (bid < NBL) {
        // ================= scanner: labels ONLY, publish flag ===============
        const int n4   = N >> 2;
        const int perl = (n4 + NBL - 1) / NBL;         // ~1563 -> 2 loads/thr
        const int ll = bid * perl;
        const int lh = min(n4, ll + perl);
        const int4* l4 = (const int4*)labels;
        for (int i = ll + t; i < lh; i += NT) {
            int4 lv = __ldg(l4 + i);
            if ((lv.x | lv.y | lv.z | lv.w) != 0) {    // the one-hot hit
                int idx = 4 * i;
                if      (lv.y != 0) idx += 1;
                else if (lv.z != 0) idx += 2;
                else if (lv.w != 0) idx += 3;
                float2 xt = __ldg((const float2*)(x + 2 * idx));
                g_target = idx;
                g_xt0 = xt.x;
                g_xt1 = xt.y;
                __threadfence();                       // target before flag
                g_tflag = 1;
            }
        }
        if (bid == 0) {   // scalar tail (N % 4)
            for (int i = (n4 << 2) + t; i < N; i += NT) {
                if (__ldg(labels + i) != 0) {
                    float2 xt = __ldg((const float2*)(x + 2 * i));
                    g_target = i;
                    g_xt0 = xt.x;
                    g_xt1 = xt.y;
                    __threadfence();
                    g_tflag = 1;
                }
            }
        }
        // idle scanners warm L2 with Wfc (8 blocks x 2 float4/thr == 256KB)
        {
            const float4* wf4 = (const float4*)Wfc;
            prefetch_l2(wf4 + bid * (2 * NT) + t);
            prefetch_l2(wf4 + bid * (2 * NT) + NT + t);
        }
        return;                                        // scanners don't ticket
    }

    if (bid != TAILB) {
        // ================= worker: dst filter ===============================
        __shared__ int sTarget;
        const int w    = bid - NBL;
        const int e4   = E >> 2;
        const int per  = (e4 + NBW - 1) / NBW;         // ~3226 -> 4 loads/thr
        const int lo   = w * per;
        const int hi   = min(e4, lo + per);
        const int4* d4 = (const int4*)dstp;
        int4 v0, v1, v2, v3;
        bool h0 = false, h1 = false, h2 = false, h3 = false;
        const int i0 = lo + t, i1 = i0 + NT, i2 = i1 + NT, i3 = i2 + NT;
        if (i0 < hi) { v0 = __ldg(d4 + i0); h0 = true; }
        if (i1 < hi) { v1 = __ldg(d4 + i1); h1 = true; }
        if (i2 < hi) { v2 = __ldg(d4 + i2); h2 = true; }
        if (i3 < hi) { v3 = __ldg(d4 + i3); h3 = true; }

        // wait for target (expected ~0 wait), compare in registers
        if (t == 0) {
            while (g_tflag == 0) {}
            __threadfence();                           // acquire
            sTarget = g_target;
        }
        __syncthreads();
        const int target = sTarget;

        if (h0) check4(v0, 4 * i0, target, srcp, x, eattr);
        if (h1) check4(v1, 4 * i1, target, srcp, x, eattr);
        if (h2) check4(v2, 4 * i2, target, srcp, x, eattr);
        if (h3) check4(v3, 4 * i3, target, srcp, x, eattr);
        if (w == 0) {   // scalar tail (E % 4)
            for (int i = (e4 << 2) + t; i < E; i += NT)
                if (__ldg(dstp + i) == target) record_match(i, srcp, x, eattr);
        }

        __syncthreads();
        if (t == 0) {
            __threadfence();                           // publish before ticket
            atomicAdd((unsigned*)&g_ticket, 1u);
        }
        return;                                        // workers retire
    }

    // ================= dedicated tail block (bid == TAILB) ==================
    __shared__ float  sWl0[HC], sWl1[HC], sbl[HC], sWe[HC], satt[HC];
    __shared__ float  sXr[HC], sbo[HC], sbfc[HC];
    __shared__ int    sEid[MAXED];
    __shared__ float  sX0[MAXED], sX1[MAXED], sEa[MAXED];
    __shared__ float  sAlpha[MAXED * 2];
    __shared__ float  sTe[HC];
    __shared__ float4 sP4[NT];
    __shared__ int    sTot;
    __shared__ float  sXt0s, sXt1s;

    // prefetch Wfc from here too (redundant with scanners, harmless)
    for (int i = t; i < (HC * HID) >> 2; i += NT)
        prefetch_l2(((const float4*)Wfc) + i);

    // Phase A (overlaps workers' filtering): wait for target, preload ALL
    // tail weights into smem and compute sXr.
    if (t == 0) {
        while (g_tflag == 0) {}
        __threadfence();                               // acquire
        sXt0s = g_xt0;
        sXt1s = g_xt1;
    }
    __syncthreads();
    if (t < HC) {
        sWl0[t] = Wl[t];
        sWl1[t] = Wl[HC + t];
        sbl[t]  = bl[t];
        sWe[t]  = We[t];
        satt[t] = att[t];
        sbo[t]  = bo[t];
        sbfc[t] = bfc[t];
        sXr[t]  = sXt0s * Wr[t] + sXt1s * Wr[HC + t] + br[t];
    }

    // Phase B: wait for all workers to ticket, then grab the match records.
    if (t == 0) {
        while (g_ticket != NBW) {}
        __threadfence();                               // acquire
        sTot = min(g_count, MAXED);
        g_count  = 0;                                  // replay-safe resets
        *((unsigned*)&g_ticket) = 0;
        g_tflag  = 0;
    }
    __syncthreads();
    const int cnt = sTot;
    if (t < MAXED) {
        sEid[t] = g_eid[t];
        sX0[t]  = g_ex0[t];
        sX1[t]  = g_ex1[t];
        sEa[t]  = g_eea[t];
    }
    __syncthreads();

    // thread-0 insertion sort by eid with payloads (cnt ~ 8);
    // ascending eid = reference segment_sum order (bit-deterministic)
    if (t == 0) {
        for (int a = 1; a < cnt; a++) {
            int   ke = sEid[a];
            float k0 = sX0[a], k1 = sX1[a], ka = sEa[a];
            int b = a - 1;
            while (b >= 0 && sEid[b] > ke) {
                sEid[b+1] = sEid[b]; sX0[b+1] = sX0[b];
                sX1[b+1] = sX1[b];   sEa[b+1] = sEa[b];
                b--;
            }
            sEid[b+1] = ke; sX0[b+1] = k0; sX1[b+1] = k1; sEa[b+1] = ka;
        }
    }
    __syncthreads();

    // attention logits: one warp per (edge, head); all weights in smem
    {
        const int wid = t >> 5, lane = t & 31;
        for (int p = wid; p < 2 * cnt; p += 32) {
            const int e = p >> 1, h = p & 1;
            const float xs0 = sX0[e], xs1 = sX1[e], ea = sEa[e];
            float acc = 0.0f;
            #pragma unroll
            for (int i = 0; i < 4; i++) {
                const int c = h * 128 + lane + 32 * i;
                const float xl = xs0 * sWl0[c] + xs1 * sWl1[c] + sbl[c];
                float m = xl + sXr[c] + ea * sWe[c];
                float lv = m > 0.0f ? m : 0.2f * m;
                acc += lv * satt[c];
            }
            #pragma unroll
            for (int st = 16; st > 0; st >>= 1)
                acc += __shfl_down_sync(0xFFFFFFFFu, acc, st);
            if (lane == 0) sAlpha[e * 2 + h] = acc;
        }
    }
    __syncthreads();

    // per-head softmax (reference quirks; __expf: MUFU, err ~5e-7 << 1e-3)
    if (t < 2) {
        const int h = t;
        float amax = -INFINITY;
        for (int e = 0; e < cnt; e++) amax = fmaxf(amax, sAlpha[e * 2 + h]);
        if (!isfinite(amax)) amax = 0.0f;
        float den = 0.0f;
        for (int e = 0; e < cnt; e++) den += __expf(sAlpha[e * 2 + h] - amax);
        const float inv = 1.0f / (den + 1e-16f);
        for (int e = 0; e < cnt; e++)
            sAlpha[e * 2 + h] = __expf(sAlpha[e * 2 + h] - amax) * inv;
    }
    __syncthreads();

    // weighted message sum (ascending edge order), bias, ReLU — smem weights
    if (t < HC) {
        const int j = t, h = j >> 7;
        const float Wl0 = sWl0[j], Wl1 = sWl1[j], blj = sbl[j];
        float acc = 0.0f;
        for (int e = 0; e < cnt; e++) {
            const float xl = sX0[e] * Wl0 + sX1[e] * Wl1 + blj;
            acc += xl * sAlpha[e * 2 + h];
        }
        sTe[j] = fmaxf(acc + sbo[j], 0.0f);
    }
    __syncthreads();

    // FC with float4 loads: thread t -> column-quad (t&63), k-chunk (t>>6)
    {
        const int j4 = t & 63, g = t >> 6;
        const float4* Wfc4 = (const float4*)Wfc;
        float4 acc = make_float4(0.f, 0.f, 0.f, 0.f);
        const int k0 = g * 16;
        #pragma unroll
        for (int k = k0; k < k0 + 16; k++) {
            float4 w = Wfc4[k * 64 + j4];
            float tv = sTe[k];
            acc.x += tv * w.x; acc.y += tv * w.y;
            acc.z += tv * w.z; acc.w += tv * w.w;
        }
        sP4[g * 64 + j4] = acc;
    }
    __syncthreads();
    if (t < HID) {
        const int j4 = t >> 2, c = t & 3;
        float s = sbfc[t];
        #pragma unroll
        for (int g = 0; g < 16; g++) {                 // fixed order
            const float* p = (const float*)&sP4[g * 64 + j4];
            s += p[c];
        }
        out[t] = s;
    }
}

// ---------------------------------------------------------------------------
extern "C" void kernel_launch(void* const* d_in, const int* in_sizes, int n_in,
                              void* d_out, int out_size)
{
    const float* x          = (const float*)d_in[0];
    const int*   edge_index = (const int*)  d_in[1];
    const float* edge_attr  = (const float*)d_in[2];
    const int*   labels     = (const int*)  d_in[3];
    // conv1 params d_in[4..10] are dead code (h1 overwritten in reference)
    const float* Wl2 = (const float*)d_in[11];
    const float* bl2 = (const float*)d_in[12];
    const float* Wr2 = (const float*)d_in[13];
    const float* br2 = (const float*)d_in[14];
    const float* We2 = (const float*)d_in[15];
    const float* att2= (const float*)d_in[16];
    const float* bo2 = (const float*)d_in[17];
    const float* Wfc = (const float*)d_in[18];
    const float* bfc = (const float*)d_in[19];
    float* out = (float*)d_out;

    const int E = in_sizes[1] / 2;

    gat_kernel<<<NB, NT>>>(x, edge_index, edge_attr, labels,
                           Wl2, bl2, Wr2, br2, We2, att2, bo2,
                           Wfc, bfc, out, in_sizes[3], E);
}

// round 15
// speedup vs baseline: 1.0244x; 1.0244x over previous
#include <cuda_runtime.h>
#include <math.h>
#include <stdint.h>

#define NB    148     // grid: one wave, 1 block/SM
#define NT    1024
#define NBL   16      // scanner blocks (labels)
#define TAILB (NB - 1)                 // dedicated tail block
#define NBW   (NB - 1 - NBL)           // worker blocks: 131
#define HC    256     // H*C = 2*128
#define HID   256
#define MAXED 256     // cap on edges into target (expected ~8)

// __device__ scratch. g_count/g_ticket/g_tflag reset by the tail block.
__device__ int      g_target;
__device__ float    g_xt0, g_xt1;
__device__ volatile int g_tflag;       // 0 -> target not yet published
__device__ int      g_count;
__device__ int      g_eid[MAXED];
__device__ float    g_ex0[MAXED], g_ex1[MAXED], g_eea[MAXED];
__device__ volatile unsigned g_ticket; // counts workers that finished

__device__ __forceinline__ void prefetch_l2(const void* p) {
    asm volatile("prefetch.global.L2 [%0];" :: "l"(p));
}

// On a match, fetch everything the tail needs (overlaps other blocks' work).
__device__ __forceinline__ void record_match(
    int eid, const int* src, const float* x, const float* eattr)
{
    int p = atomicAdd(&g_count, 1);
    if (p < MAXED) {
        int s = __ldg(src + eid);
        float2 xs = __ldg((const float2*)(x + 2 * s));
        g_eid[p] = eid;
        g_ex0[p] = xs.x;
        g_ex1[p] = xs.y;
        g_eea[p] = __ldg(eattr + eid);
    }
}

// ---------------------------------------------------------------------------
__global__ void __launch_bounds__(NT, 1) gat_kernel(
    const float* __restrict__ x,
    const int*   __restrict__ edge_index,
    const float* __restrict__ eattr,
    const int*   __restrict__ labels,
    const float* __restrict__ Wl,  const float* __restrict__ bl,
    const float* __restrict__ Wr,  const float* __restrict__ br,
    const float* __restrict__ We,  const float* __restrict__ att,
    const float* __restrict__ bo,
    const float* __restrict__ Wfc, const float* __restrict__ bfc,
    float* __restrict__ out, int N, int E)
{
    const int t   = threadIdx.x;
    const int bid = blockIdx.x;
    const int* srcp = edge_index;
    const int* dstp = edge_index + E;

    if (bid < NBL) {
        // ================= scanner: labels ONLY, publish flag ===============
        const int n4   = N >> 2;
        const int perl = (n4 + NBL - 1) / NBL;         // ~782 -> 1 load/thread
        const int ll = bid * perl;
        const int lh = min(n4, ll + perl);
        const int4* l4 = (const int4*)labels;
        for (int i = ll + t; i < lh; i += NT) {
            int4 lv = __ldg(l4 + i);
            if ((lv.x | lv.y | lv.z | lv.w) != 0) {    // the one-hot hit
                int idx = 4 * i;
                if      (lv.y != 0) idx += 1;
                else if (lv.z != 0) idx += 2;
                else if (lv.w != 0) idx += 3;
                float2 xt = __ldg((const float2*)(x + 2 * idx));
                g_target = idx;
                g_xt0 = xt.x;
                g_xt1 = xt.y;
                __threadfence();                       // target before flag
                g_tflag = 1;
            }
        }
        if (bid == 0) {   // scalar tail (N % 4)
            for (int i = (n4 << 2) + t; i < N; i += NT) {
                if (__ldg(labels + i) != 0) {
                    float2 xt = __ldg((const float2*)(x + 2 * i));
                    g_target = i;
                    g_xt0 = xt.x;
                    g_xt1 = xt.y;
                    __threadfence();
                    g_tflag = 1;
                }
            }
        }
        // idle scanners warm L2 with Wfc (16*1024 float4 == 256KB exactly)
        prefetch_l2(((const float4*)Wfc) + bid * NT + t);
        return;                                        // scanners don't ticket
    }

    if (bid != TAILB) {
        // ================= worker: dst filter ===============================
        __shared__ int sTarget;
        const int w    = bid - NBL;
        const int e4   = E >> 2;
        const int per  = (e4 + NBW - 1) / NBW;         // ~764 -> 1 quad/thread
        const int lo   = w * per;
        const int hi   = min(e4, lo + per);
        const int4* d4 = (const int4*)dstp;
        int4 v0, v1; bool h0 = false, h1 = false;
        const int i0 = lo + t, i1 = i0 + NT;
        if (i0 < hi) { v0 = __ldg(d4 + i0); h0 = true; }
        if (i1 < hi) { v1 = __ldg(d4 + i1); h1 = true; }

        // wait for target (expected ~0 wait), compare in registers
        if (t == 0) {
            while (g_tflag == 0) {}
            __threadfence();                           // acquire
            sTarget = g_target;
        }
        __syncthreads();
        const int target = sTarget;

        if (h0) {
            int base = 4 * i0;
            if (v0.x == target) record_match(base,     srcp, x, eattr);
            if (v0.y == target) record_match(base + 1, srcp, x, eattr);
            if (v0.z == target) record_match(base + 2, srcp, x, eattr);
            if (v0.w == target) record_match(base + 3, srcp, x, eattr);
        }
        if (h1) {
            int base = 4 * i1;
            if (v1.x == target) record_match(base,     srcp, x, eattr);
            if (v1.y == target) record_match(base + 1, srcp, x, eattr);
            if (v1.z == target) record_match(base + 2, srcp, x, eattr);
            if (v1.w == target) record_match(base + 3, srcp, x, eattr);
        }
        if (w == 0) {   // scalar tail (E % 4)
            for (int i = (e4 << 2) + t; i < E; i += NT)
                if (__ldg(dstp + i) == target) record_match(i, srcp, x, eattr);
        }

        __syncthreads();                               // all matches recorded
        if (t == 0) {
            __threadfence();                           // publish before ticket
            atomicAdd((unsigned*)&g_ticket, 1u);
        }
        return;                                        // workers retire
    }

    // ================= dedicated tail block (bid == TAILB) ==================
    __shared__ float  sWl0[HC], sWl1[HC], sbl[HC], sWe[HC], satt[HC];
    __shared__ float  sWr0[HC], sWr1[HC], sbr[HC];
    __shared__ float  sXr[HC], sbo[HC], sbfc[HC];
    __shared__ int    sEid[MAXED];
    __shared__ float  sX0[MAXED], sX1[MAXED], sEa[MAXED];
    __shared__ float  sAlpha[MAXED * 2];
    __shared__ float  sTe[HC];
    __shared__ float4 sP4[NT];
    __shared__ int    sTot;
    __shared__ float  sXt0s, sXt1s;

    // Phase A0: issue ALL target-independent weight loads IMMEDIATELY —
    // they fly during the flag wait. (No redundant Wfc prefetch here.)
    if (t < HC) {
        sWl0[t] = Wl[t];
        sWl1[t] = Wl[HC + t];
        sbl[t]  = bl[t];
        sWe[t]  = We[t];
        satt[t] = att[t];
        sWr0[t] = Wr[t];
        sWr1[t] = Wr[HC + t];
        sbr[t]  = br[t];
        sbo[t]  = bo[t];
        sbfc[t] = bfc[t];
    }

    // Phase A1: wait for target, then the only target-dependent prep (sXr).
    if (t == 0) {
        while (g_tflag == 0) {}
        __threadfence();                               // acquire
        sXt0s = g_xt0;
        sXt1s = g_xt1;
    }
    __syncthreads();
    if (t < HC)
        sXr[t] = sXt0s * sWr0[t] + sXt1s * sWr1[t] + sbr[t];

    // Phase B: wait for all workers to ticket, then grab the match records.
    if (t == 0) {
        while (g_ticket != NBW) {}
        __threadfence();                               // acquire
        sTot = min(g_count, MAXED);
        g_count  = 0;                                  // replay-safe resets
        *((unsigned*)&g_ticket) = 0;
        g_tflag  = 0;
    }
    __syncthreads();
    const int cnt = sTot;
    if (t < MAXED) {
        sEid[t] = g_eid[t];
        sX0[t]  = g_ex0[t];
        sX1[t]  = g_ex1[t];
        sEa[t]  = g_eea[t];
    }
    __syncthreads();

    // thread-0 insertion sort by eid with payloads (cnt ~ 8);
    // ascending eid = reference segment_sum order (bit-deterministic)
    if (t == 0) {
        for (int a = 1; a < cnt; a++) {
            int   ke = sEid[a];
            float k0 = sX0[a], k1 = sX1[a], ka = sEa[a];
            int b = a - 1;
            while (b >= 0 && sEid[b] > ke) {
                sEid[b+1] = sEid[b]; sX0[b+1] = sX0[b];
                sX1[b+1] = sX1[b];   sEa[b+1] = sEa[b];
                b--;
            }
            sEid[b+1] = ke; sX0[b+1] = k0; sX1[b+1] = k1; sEa[b+1] = ka;
        }
    }
    __syncthreads();

    // attention logits: one warp per (edge, head); all weights in smem
    {
        const int wid = t >> 5, lane = t & 31;
        for (int p = wid; p < 2 * cnt; p += 32) {
            const int e = p >> 1, h = p & 1;
            const float xs0 = sX0[e], xs1 = sX1[e], ea = sEa[e];
            float acc = 0.0f;
            #pragma unroll
            for (int i = 0; i < 4; i++) {
                const int c = h * 128 + lane + 32 * i;
                const float xl = xs0 * sWl0[c] + xs1 * sWl1[c] + sbl[c];
                float m = xl + sXr[c] + ea * sWe[c];
                float lv = m > 0.0f ? m : 0.2f * m;
                acc += lv * satt[c];
            }
            #pragma unroll
            for (int st = 16; st > 0; st >>= 1)
                acc += __shfl_down_sync(0xFFFFFFFFu, acc, st);
            if (lane == 0) sAlpha[e * 2 + h] = acc;
        }
    }
    __syncthreads();

    // per-head softmax (reference quirks; __expf: MUFU, err ~5e-7 << 1e-3)
    if (t < 2) {
        const int h = t;
        float amax = -INFINITY;
        for (int e = 0; e < cnt; e++) amax = fmaxf(amax, sAlpha[e * 2 + h]);
        if (!isfinite(amax)) amax = 0.0f;
        float den = 0.0f;
        for (int e = 0; e < cnt; e++) den += __expf(sAlpha[e * 2 + h] - amax);
        const float inv = 1.0f / (den + 1e-16f);
        for (int e = 0; e < cnt; e++)
            sAlpha[e * 2 + h] = __expf(sAlpha[e * 2 + h] - amax) * inv;
    }
    __syncthreads();

    // weighted message sum (ascending edge order), bias, ReLU — smem weights
    if (t < HC) {
        const int j = t, h = j >> 7;
        const float Wl0 = sWl0[j], Wl1 = sWl1[j], blj = sbl[j];
        float acc = 0.0f;
        for (int e = 0; e < cnt; e++) {
            const float xl = sX0[e] * Wl0 + sX1[e] * Wl1 + blj;
            acc += xl * sAlpha[e * 2 + h];
        }
        sTe[j] = fmaxf(acc + sbo[j], 0.0f);
    }
    __syncthreads();

    // FC with float4 loads: thread t -> column-quad (t&63), k-chunk (t>>6)
    {
        const int j4 = t & 63, g = t >> 6;
        const float4* Wfc4 = (const float4*)Wfc;       // L2-warm via scanners
        float4 acc = make_float4(0.f, 0.f, 0.f, 0.f);
        const int k0 = g * 16;
        #pragma unroll
        for (int k = k0; k < k0 + 16; k++) {
            float4 w = Wfc4[k * 64 + j4];
            float tv = sTe[k];
            acc.x += tv * w.x; acc.y += tv * w.y;
            acc.z += tv * w.z; acc.w += tv * w.w;
        }
        sP4[g * 64 + j4] = acc;
    }
    __syncthreads();
    if (t < HID) {
        const int j4 = t >> 2, c = t & 3;
        float s = sbfc[t];
        #pragma unroll
        for (int g = 0; g < 16; g++) {                 // fixed order
            const float* p = (const float*)&sP4[g * 64 + j4];
            s += p[c];
        }
        out[t] = s;
    }
}

// ---------------------------------------------------------------------------
extern "C" void kernel_launch(void* const* d_in, const int* in_sizes, int n_in,
                              void* d_out, int out_size)
{
    const float* x          = (const float*)d_in[0];
    const int*   edge_index = (const int*)  d_in[1];
    const float* edge_attr  = (const float*)d_in[2];
    const int*   labels     = (const int*)  d_in[3];
    // conv1 params d_in[4..10] are dead code (h1 overwritten in reference)
    const float* Wl2 = (const float*)d_in[11];
    const float* bl2 = (const float*)d_in[12];
    const float* Wr2 = (const float*)d_in[13];
    const float* br2 = (const float*)d_in[14];
    const float* We2 = (const float*)d_in[15];
    const float* att2= (const float*)d_in[16];
    const float* bo2 = (const float*)d_in[17];
    const float* Wfc = (const float*)d_in[18];
    const float* bfc = (const float*)d_in[19];
    float* out = (float*)d_out;

    const int E = in_sizes[1] / 2;

    gat_kernel<<<NB, NT>>>(x, edge_index, edge_attr, labels,
                           Wl2, bl2, Wr2, br2, We2, att2, bo2,
                           Wfc, bfc, out, in_sizes[3], E);
}

// round 16
// speedup vs baseline: 1.0528x; 1.0276x over previous
#include <cuda_runtime.h>
#include <math.h>
#include <stdint.h>

#define NB    148     // grid: one wave, 1 block/SM
#define NT    1024
#define NBL   16      // scanner blocks (labels)
#define TAILB (NB - 1)                 // dedicated tail block
#define NBW   (NB - 1 - NBL)           // worker blocks: 131
#define HC    256     // H*C = 2*128
#define HID   256
#define MAXED 256     // cap on edges into target (expected ~8)

// __device__ scratch. g_count/g_ticket/g_tflag reset by the tail block.
__device__ int      g_target;
__device__ volatile int g_tflag;       // 0 -> target not yet published
__device__ int      g_count;
__device__ int      g_eid[MAXED];
__device__ float    g_ex0[MAXED], g_ex1[MAXED], g_eea[MAXED];
__device__ volatile unsigned g_ticket; // counts workers that finished

__device__ __forceinline__ void prefetch_l2(const void* p) {
    asm volatile("prefetch.global.L2 [%0];" :: "l"(p));
}

// On a match, fetch everything the tail needs (overlaps other blocks' work).
__device__ __forceinline__ void record_match(
    int eid, const int* src, const float* x, const float* eattr)
{
    int p = atomicAdd(&g_count, 1);
    if (p < MAXED) {
        int s = __ldg(src + eid);
        float2 xs = __ldg((const float2*)(x + 2 * s));
        g_eid[p] = eid;
        g_ex0[p] = xs.x;
        g_ex1[p] = xs.y;
        g_eea[p] = __ldg(eattr + eid);
    }
}

// ---------------------------------------------------------------------------
__global__ void __launch_bounds__(NT, 1) gat_kernel(
    const float* __restrict__ x,
    const int*   __restrict__ edge_index,
    const float* __restrict__ eattr,
    const int*   __restrict__ labels,
    const float* __restrict__ Wl,  const float* __restrict__ bl,
    const float* __restrict__ Wr,  const float* __restrict__ br,
    const float* __restrict__ We,  const float* __restrict__ att,
    const float* __restrict__ bo,
    const float* __restrict__ Wfc, const float* __restrict__ bfc,
    float* __restrict__ out, int N, int E)
{
    const int t   = threadIdx.x;
    const int bid = blockIdx.x;
    const int* srcp = edge_index;
    const int* dstp = edge_index + E;

    if (bid < NBL) {
        // ====== scanner: labels ONLY; publish flag IMMEDIATELY on hit =======
        // (x[target] is NOT loaded here — the tail loads it; this removes one
        //  dependent DRAM round trip from the grid-wide flag critical path.)
        const int n4   = N >> 2;
        const int perl = (n4 + NBL - 1) / NBL;         // ~782 -> 1 load/thread
        const int ll = bid * perl;
        const int lh = min(n4, ll + perl);
        const int4* l4 = (const int4*)labels;
        for (int i = ll + t; i < lh; i += NT) {
            int4 lv = __ldg(l4 + i);
            if ((lv.x | lv.y | lv.z | lv.w) != 0) {    // the one-hot hit
                int idx = 4 * i;
                if      (lv.y != 0) idx += 1;
                else if (lv.z != 0) idx += 2;
                else if (lv.w != 0) idx += 3;
                g_target = idx;
                __threadfence();                       // target before flag
                g_tflag = 1;
            }
        }
        if (bid == 0) {   // scalar tail (N % 4)
            for (int i = (n4 << 2) + t; i < N; i += NT) {
                if (__ldg(labels + i) != 0) {
                    g_target = i;
                    __threadfence();
                    g_tflag = 1;
                }
            }
        }
        // idle scanners warm L2 with Wfc (16*1024 float4 == 256KB exactly)
        prefetch_l2(((const float4*)Wfc) + bid * NT + t);
        return;                                        // scanners don't ticket
    }

    if (bid != TAILB) {
        // ================= worker: dst filter ===============================
        __shared__ int sTarget;
        const int w    = bid - NBL;
        const int e4   = E >> 2;
        const int per  = (e4 + NBW - 1) / NBW;         // ~764 -> 1 quad/thread
        const int lo   = w * per;
        const int hi   = min(e4, lo + per);
        const int4* d4 = (const int4*)dstp;
        int4 v0, v1; bool h0 = false, h1 = false;
        const int i0 = lo + t, i1 = i0 + NT;
        if (i0 < hi) { v0 = __ldg(d4 + i0); h0 = true; }
        if (i1 < hi) { v1 = __ldg(d4 + i1); h1 = true; }

        // wait for target (expected ~0 wait), compare in registers
        if (t == 0) {
            while (g_tflag == 0) {}
            __threadfence();                           // acquire
            sTarget = g_target;
        }
        __syncthreads();
        const int target = sTarget;

        if (h0) {
            int base = 4 * i0;
            if (v0.x == target) record_match(base,     srcp, x, eattr);
            if (v0.y == target) record_match(base + 1, srcp, x, eattr);
            if (v0.z == target) record_match(base + 2, srcp, x, eattr);
            if (v0.w == target) record_match(base + 3, srcp, x, eattr);
        }
        if (h1) {
            int base = 4 * i1;
            if (v1.x == target) record_match(base,     srcp, x, eattr);
            if (v1.y == target) record_match(base + 1, srcp, x, eattr);
            if (v1.z == target) record_match(base + 2, srcp, x, eattr);
            if (v1.w == target) record_match(base + 3, srcp, x, eattr);
        }
        if (w == 0) {   // scalar tail (E % 4)
            for (int i = (e4 << 2) + t; i < E; i += NT)
                if (__ldg(dstp + i) == target) record_match(i, srcp, x, eattr);
        }

        __syncthreads();                               // all matches recorded
        if (t == 0) {
            __threadfence();                           // publish before ticket
            atomicAdd((unsigned*)&g_ticket, 1u);
        }
        return;                                        // workers retire
    }

    // ================= dedicated tail block (bid == TAILB) ==================
    __shared__ float  sWl0[HC], sWl1[HC], sbl[HC], sWe[HC], satt[HC];
    __shared__ float  sWr0[HC], sWr1[HC], sbr[HC];
    __shared__ float  sXr[HC], sbo[HC], sbfc[HC];
    __shared__ int    sEid[MAXED];
    __shared__ float  sX0[MAXED], sX1[MAXED], sEa[MAXED];
    __shared__ float  sAlpha[MAXED * 2];
    __shared__ float  sTe[HC];
    __shared__ float4 sP4[NT];
    __shared__ int    sTot;
    __shared__ float  sXt0s, sXt1s;

    // Phase A0: issue ALL target-independent weight loads IMMEDIATELY —
    // they fly during the flag wait.
    if (t < HC) {
        sWl0[t] = Wl[t];
        sWl1[t] = Wl[HC + t];
        sbl[t]  = bl[t];
        sWe[t]  = We[t];
        satt[t] = att[t];
        sWr0[t] = Wr[t];
        sWr1[t] = Wr[HC + t];
        sbr[t]  = br[t];
        sbo[t]  = bo[t];
        sbfc[t] = bfc[t];
    }

    // Phase A1: wait for flag, load x[target] HERE (tail has slack before the
    // ticket wait; this load is off the grid-wide critical path), compute sXr.
    if (t == 0) {
        while (g_tflag == 0) {}
        __threadfence();                               // acquire
        float2 xt = __ldg((const float2*)(x + 2 * g_target));
        sXt0s = xt.x;
        sXt1s = xt.y;
    }
    __syncthreads();
    if (t < HC)
        sXr[t] = sXt0s * sWr0[t] + sXt1s * sWr1[t] + sbr[t];

    // Phase B: wait for all workers to ticket, then grab the match records.
    if (t == 0) {
        while (g_ticket != NBW) {}
        __threadfence();                               // acquire
        sTot = min(g_count, MAXED);
        g_count  = 0;                                  // replay-safe resets
        *((unsigned*)&g_ticket) = 0;
        g_tflag  = 0;
    }
    __syncthreads();
    const int cnt = sTot;
    if (t < MAXED) {
        sEid[t] = g_eid[t];
        sX0[t]  = g_ex0[t];
        sX1[t]  = g_ex1[t];
        sEa[t]  = g_eea[t];
    }
    __syncthreads();

    // thread-0 insertion sort by eid with payloads (cnt ~ 8);
    // ascending eid = reference segment_sum order (bit-deterministic)
    if (t == 0) {
        for (int a = 1; a < cnt; a++) {
            int   ke = sEid[a];
            float k0 = sX0[a], k1 = sX1[a], ka = sEa[a];
            int b = a - 1;
            while (b >= 0 && sEid[b] > ke) {
                sEid[b+1] = sEid[b]; sX0[b+1] = sX0[b];
                sX1[b+1] = sX1[b];   sEa[b+1] = sEa[b];
                b--;
            }
            sEid[b+1] = ke; sX0[b+1] = k0; sX1[b+1] = k1; sEa[b+1] = ka;
        }
    }
    __syncthreads();

    // attention logits: one warp per (edge, head); all weights in smem
    {
        const int wid = t >> 5, lane = t & 31;
        for (int p = wid; p < 2 * cnt; p += 32) {
            const int e = p >> 1, h = p & 1;
            const float xs0 = sX0[e], xs1 = sX1[e], ea = sEa[e];
            float acc = 0.0f;
            #pragma unroll
            for (int i = 0; i < 4; i++) {
                const int c = h * 128 + lane + 32 * i;
                const float xl = xs0 * sWl0[c] + xs1 * sWl1[c] + sbl[c];
                float m = xl + sXr[c] + ea * sWe[c];
                float lv = m > 0.0f ? m : 0.2f * m;
                acc += lv * satt[c];
            }
            #pragma unroll
            for (int st = 16; st > 0; st >>= 1)
                acc += __shfl_down_sync(0xFFFFFFFFu, acc, st);
            if (lane == 0) sAlpha[e * 2 + h] = acc;
        }
    }
    __syncthreads();

    // per-head softmax (reference quirks; __expf: MUFU, err ~5e-7 << 1e-3)
    if (t < 2) {
        const int h = t;
        float amax = -INFINITY;
        for (int e = 0; e < cnt; e++) amax = fmaxf(amax, sAlpha[e * 2 + h]);
        if (!isfinite(amax)) amax = 0.0f;
        float den = 0.0f;
        for (int e = 0; e < cnt; e++) den += __expf(sAlpha[e * 2 + h] - amax);
        const float inv = 1.0f / (den + 1e-16f);
        for (int e = 0; e < cnt; e++)
            sAlpha[e * 2 + h] = __expf(sAlpha[e * 2 + h] - amax) * inv;
    }
    __syncthreads();

    // weighted message sum (ascending edge order), bias, ReLU — smem weights
    if (t < HC) {
        const int j = t, h = j >> 7;
        const float Wl0 = sWl0[j], Wl1 = sWl1[j], blj = sbl[j];
        float acc = 0.0f;
        for (int e = 0; e < cnt; e++) {
            const float xl = sX0[e] * Wl0 + sX1[e] * Wl1 + blj;
            acc += xl * sAlpha[e * 2 + h];
        }
        sTe[j] = fmaxf(acc + sbo[j], 0.0f);
    }
    __syncthreads();

    // FC with float4 loads: thread t -> column-quad (t&63), k-chunk (t>>6)
    {
        const int j4 = t & 63, g = t >> 6;
        const float4* Wfc4 = (const float4*)Wfc;       // L2-warm via scanners
        float4 acc = make_float4(0.f, 0.f, 0.f, 0.f);
        const int k0 = g * 16;
        #pragma unroll
        for (int k = k0; k < k0 + 16; k++) {
            float4 w = Wfc4[k * 64 + j4];
            float tv = sTe[k];
            acc.x += tv * w.x; acc.y += tv * w.y;
            acc.z += tv * w.z; acc.w += tv * w.w;
        }
        sP4[g * 64 + j4] = acc;
    }
    __syncthreads();
    if (t < HID) {
        const int j4 = t >> 2, c = t & 3;
        float s = sbfc[t];
        #pragma unroll
        for (int g = 0; g < 16; g++) {                 // fixed order
            const float* p = (const float*)&sP4[g * 64 + j4];
            s += p[c];
        }
        out[t] = s;
    }
}

// ---------------------------------------------------------------------------
extern "C" void kernel_launch(void* const* d_in, const int* in_sizes, int n_in,
                              void* d_out, int out_size)
{
    const float* x          = (const float*)d_in[0];
    const int*   edge_index = (const int*)  d_in[1];
    const float* edge_attr  = (const float*)d_in[2];
    const int*   labels     = (const int*)  d_in[3];
    // conv1 params d_in[4..10] are dead code (h1 overwritten in reference)
    const float* Wl2 = (const float*)d_in[11];
    const float* bl2 = (const float*)d_in[12];
    const float* Wr2 = (const float*)d_in[13];
    const float* br2 = (const float*)d_in[14];
    const float* We2 = (const float*)d_in[15];
    const float* att2= (const float*)d_in[16];
    const float* bo2 = (const float*)d_in[17];
    const float* Wfc = (const float*)d_in[18];
    const float* bfc = (const float*)d_in[19];
    float* out = (float*)d_out;

    const int E = in_sizes[1] / 2;

    gat_kernel<<<NB, NT>>>(x, edge_index, edge_attr, labels,
                           Wl2, bl2, Wr2, br2, We2, att2, bo2,
                           Wfc, bfc, out, in_sizes[3], E);
}